// round 1
// baseline (speedup 1.0000x reference)
#include <cuda_runtime.h>

#define LH 150
#define LQ 10
#define KI 10
#define NWARP 8

// Effective 3x3 kernel (collapses the 150-channel hidden conv + 1x1 readout)
// g_weff[0..8] = sum_c Wr[c]*Wh[c][k],  g_weff[9] = sum_c Wr[c]*bh[c]
__device__ float g_weff[10];

__global__ void weff_kernel(const float* __restrict__ Wh,
                            const float* __restrict__ bh,
                            const float* __restrict__ Wr) {
    int t = threadIdx.x;
    if (t < 9) {
        float acc = 0.f;
        for (int c = 0; c < LH; ++c) acc = fmaf(Wr[c], Wh[c * 9 + t], acc);
        g_weff[t] = acc;
    } else if (t == 9) {
        float acc = 0.f;
        for (int c = 0; c < LH; ++c) acc = fmaf(Wr[c], bh[c], acc);
        g_weff[9] = acc;
    }
}

// One warp per batch element. Lane l owns pixels p0 = l and p1 = l + 32
// (same column, rows y and y+4). v-grid lives in a zero-padded 10x10 SMEM
// tile, double-buffered so each iteration needs a single __syncwarp.
__global__ __launch_bounds__(NWARP * 32)
void vin_kernel(const float* __restrict__ S,
                const float* __restrict__ Wq,
                const float* __restrict__ w,
                const float* __restrict__ Wfc,
                float* __restrict__ out, int B) {
    __shared__ float sbuf[NWARP][2][100];
    const int warp = threadIdx.x >> 5;
    const int lane = threadIdx.x & 31;
    const int b = blockIdx.x * NWARP + warp;
    if (b >= B) return;               // warp-uniform; no block barriers used
    const float* Sb = S + (long long)b * 66;
    float (*buf)[100] = sbuf[warp];

    const int y0 = lane >> 3, x0 = lane & 7;
    const int y1 = y0 + 4;
    const int i0 = (y0 + 1) * 10 + (x0 + 1);
    const int i1 = (y1 + 1) * 10 + (x0 + 1);

    // Zero both buffers (borders stay zero forever -> implicit pad=1)
    buf[0][lane] = 0.f; buf[0][lane + 32] = 0.f; buf[0][lane + 64] = 0.f;
    buf[1][lane] = 0.f; buf[1][lane + 32] = 0.f; buf[1][lane + 64] = 0.f;
    if (lane < 4) { buf[0][lane + 96] = 0.f; buf[1][lane + 96] = 0.f; }
    __syncwarp();

    // Stage X (the 8x8 grid) into buf0 interior
    buf[0][i0] = Sb[lane];
    buf[0][i1] = Sb[lane + 32];
    __syncwarp();

    // r = conv(X, W_eff, pad=1) + b_eff
    float we[9];
#pragma unroll
    for (int k = 0; k < 9; ++k) we[k] = g_weff[k];
    float r0 = g_weff[9], r1 = r0;
#pragma unroll
    for (int k = 0; k < 9; ++k) {
        const int dy = k / 3, dx = k % 3;
        r0 = fmaf(we[k], buf[0][(y0 + dy) * 10 + x0 + dx], r0);
        r1 = fmaf(we[k], buf[0][(y1 + dy) * 10 + x0 + dx], r1);
    }
    __syncwarp();
    buf[0][i0] = r0;
    buf[0][i1] = r1;
    __syncwarp();

    // qr[c] = conv(r, Wq[c], pad=1)  -- loop-invariant, kept in registers
    float qr0[LQ], qr1[LQ];
    {
        float n0[9], n1[9];
#pragma unroll
        for (int k = 0; k < 9; ++k) {
            n0[k] = buf[0][(y0 + k / 3) * 10 + x0 + k % 3];
            n1[k] = buf[0][(y1 + k / 3) * 10 + x0 + k % 3];
        }
#pragma unroll
        for (int c = 0; c < LQ; ++c) {
            float a0 = 0.f, a1 = 0.f;
#pragma unroll
            for (int k = 0; k < 9; ++k) {
                const float wq = __ldg(&Wq[c * 9 + k]);
                a0 = fmaf(wq, n0[k], a0);
                a1 = fmaf(wq, n1[k], a1);
            }
            qr0[c] = a0; qr1[c] = a1;
        }
    }

    // v0 = max_c qr
    float v0 = qr0[0], v1 = qr1[0];
#pragma unroll
    for (int c = 1; c < LQ; ++c) { v0 = fmaxf(v0, qr0[c]); v1 = fmaxf(v1, qr1[c]); }
    __syncwarp();                 // r readers done before overwrite
    buf[0][i0] = v0;
    buf[0][i1] = v1;

    // Transition weights w[10][3][3] in registers (shared by both pixels)
    float wr[LQ * 9];
#pragma unroll
    for (int i = 0; i < LQ * 9; ++i) wr[i] = __ldg(&w[i]);

    // K-1 = 9 value-iteration sweeps: v <- max_c( qr[c] + conv(v, w[c]) )
    int cur = 0;
#pragma unroll 1
    for (int it = 0; it < KI - 1; ++it) {
        __syncwarp();
        const float* vc = buf[cur];
        float n0[9], n1[9];
#pragma unroll
        for (int k = 0; k < 9; ++k) {
            n0[k] = vc[(y0 + k / 3) * 10 + x0 + k % 3];
            n1[k] = vc[(y1 + k / 3) * 10 + x0 + k % 3];
        }
        float m0, m1;
#pragma unroll
        for (int c = 0; c < LQ; ++c) {
            float a0 = qr0[c], a1 = qr1[c];
#pragma unroll
            for (int k = 0; k < 9; ++k) {
                a0 = fmaf(wr[c * 9 + k], n0[k], a0);
                a1 = fmaf(wr[c * 9 + k], n1[k], a1);
            }
            if (c == 0) { m0 = a0; m1 = a1; }
            else        { m0 = fmaxf(m0, a0); m1 = fmaxf(m1, a1); }
        }
        float* vn = buf[cur ^ 1];
        vn[i0] = m0;
        vn[i1] = m1;
        cur ^= 1;
    }
    __syncwarp();

    // Final conv at the selected pixel only + FC head (single owning lane)
    const int s1 = (int)Sb[64];
    const int s2 = (int)Sb[65];
    const int psel = s1 * 8 + s2;
    if (lane == (psel & 31)) {
        const bool hi = psel >= 32;
        const float* vc = buf[cur];
        float nn[9];
#pragma unroll
        for (int k = 0; k < 9; ++k)
            nn[k] = vc[(s1 + k / 3) * 10 + (s2 + k % 3)];
        float lg[8];
#pragma unroll
        for (int j = 0; j < 8; ++j) lg[j] = 0.f;
#pragma unroll
        for (int c = 0; c < LQ; ++c) {
            float a = hi ? qr1[c] : qr0[c];
#pragma unroll
            for (int k = 0; k < 9; ++k) a = fmaf(wr[c * 9 + k], nn[k], a);
#pragma unroll
            for (int j = 0; j < 8; ++j) lg[j] = fmaf(a, __ldg(&Wfc[j * 10 + c]), lg[j]);
        }
#pragma unroll
        for (int j = 0; j < 8; ++j) out[(long long)b * 8 + j] = lg[j];
    }
}

extern "C" void kernel_launch(void* const* d_in, const int* in_sizes, int n_in,
                              void* d_out, int out_size) {
    const float* S   = (const float*)d_in[0];
    const float* Wh  = (const float*)d_in[1];
    const float* bh  = (const float*)d_in[2];
    const float* Wr  = (const float*)d_in[3];
    const float* Wq  = (const float*)d_in[4];
    const float* w   = (const float*)d_in[5];
    const float* Wfc = (const float*)d_in[6];
    float* out = (float*)d_out;

    const int B = in_sizes[0] / 66;

    weff_kernel<<<1, 32>>>(Wh, bh, Wr);
    const int grid = (B + NWARP - 1) / NWARP;
    vin_kernel<<<grid, NWARP * 32>>>(S, Wq, w, Wfc, out, B);
}

// round 2
// speedup vs baseline: 1.0285x; 1.0285x over previous
#include <cuda_runtime.h>

typedef unsigned long long u64;

#define LH 150
#define LQ 10
#define KI 10
#define NWARP 12

// Effective 3x3 kernel (collapses 150-ch hidden conv + 1x1 readout):
// g_weff[0..8] = sum_c Wr[c]*Wh[c][k],  g_weff[9] = sum_c Wr[c]*bh[c]
__device__ float g_weff[10];

__global__ void weff_kernel(const float* __restrict__ Wh,
                            const float* __restrict__ bh,
                            const float* __restrict__ Wr) {
    const int wj = threadIdx.x >> 5;   // 0..9 : output index
    const int lane = threadIdx.x & 31;
    float acc = 0.f;
    for (int c = lane; c < LH; c += 32) {
        float x = (wj < 9) ? Wh[c * 9 + wj] : bh[c];
        acc = fmaf(Wr[c], x, acc);
    }
#pragma unroll
    for (int off = 16; off >= 1; off >>= 1)
        acc += __shfl_xor_sync(0xffffffffu, acc, off);
    if (lane == 0) g_weff[wj] = acc;
}

// ---- packed f32x2 helpers -------------------------------------------------
__device__ __forceinline__ u64 fma2(u64 a, u64 b, u64 c) {
    u64 d;
    asm("fma.rn.f32x2 %0, %1, %2, %3;" : "=l"(d) : "l"(a), "l"(b), "l"(c));
    return d;
}
__device__ __forceinline__ u64 pack2(float lo, float hi) {
    u64 r;
    asm("mov.b64 %0, {%1, %2};" : "=l"(r) : "f"(lo), "f"(hi));
    return r;
}
__device__ __forceinline__ float2 unpack2(u64 p) {
    float2 v;
    asm("mov.b64 {%0, %1}, %2;" : "=f"(v.x), "=f"(v.y) : "l"(p));
    return v;
}

// One warp per batch element. Lane l owns pixels p0=l and p1=l+32.
// v-grid lives in a zero-padded 10x10 SMEM tile of SPLAT float2 (v,v) so a
// single LDS.64 yields a broadcast-packed operand for fma.rn.f32x2.
// Channels are paired (c,c+1) into packed weights/accumulators: the 9-step
// value-iteration inner loop runs 90 FFMA2 instead of 180 FFMA.
__global__ __launch_bounds__(NWARP * 32)
void vin_kernel(const float* __restrict__ S,
                const float* __restrict__ Wq,
                const float* __restrict__ w,
                const float* __restrict__ Wfc,
                float* __restrict__ out, int B) {
    __shared__ float2 sbuf[NWARP][2][100];
    const int warp = threadIdx.x >> 5;
    const int lane = threadIdx.x & 31;
    const int b = blockIdx.x * NWARP + warp;
    if (b >= B) return;                    // warp-uniform; no block barriers
    const float* Sb = S + (long long)b * 66;

    u64* ub0 = (u64*)sbuf[warp][0];
    u64* ub1 = (u64*)sbuf[warp][1];
    float2* fb0 = sbuf[warp][0];

    const int y0 = lane >> 3, x0 = lane & 7;
    const int p0 = y0 * 10 + x0;           // 3x3 window top-left (padded grid)
    const int p1 = p0 + 40;
    const int i0 = p0 + 11;                // pixel cell
    const int i1 = i0 + 40;

    // window offsets for k = dy*3+dx
    const int OFF[9] = {0, 1, 2, 10, 11, 12, 20, 21, 22};

    // Zero both buffers (borders stay zero -> implicit pad=1)
    ub0[lane] = 0ull; ub0[lane + 32] = 0ull; ub0[lane + 64] = 0ull;
    ub1[lane] = 0ull; ub1[lane + 32] = 0ull; ub1[lane + 64] = 0ull;
    if (lane < 4) { ub0[lane + 96] = 0ull; ub1[lane + 96] = 0ull; }
    __syncwarp();

    // Stage X as splats
    {
        float xa = Sb[lane], xb = Sb[lane + 32];
        ub0[i0] = pack2(xa, xa);
        ub0[i1] = pack2(xb, xb);
    }
    __syncwarp();

    // r = conv(X, W_eff, pad=1) + b_eff   (scalar; one-shot)
    float r0 = g_weff[9], r1 = r0;
#pragma unroll
    for (int k = 0; k < 9; ++k) {
        r0 = fmaf(g_weff[k], fb0[p0 + OFF[k]].x, r0);
        r1 = fmaf(g_weff[k], fb0[p1 + OFF[k]].x, r1);
    }
    __syncwarp();
    ub0[i0] = pack2(r0, r0);
    ub0[i1] = pack2(r1, r1);
    __syncwarp();

    // Packed transition weights wp[c2][k] = {w[2c2][k], w[2c2+1][k]}
    u64 wp[45];
#pragma unroll
    for (int c2 = 0; c2 < 5; ++c2)
#pragma unroll
        for (int k = 0; k < 9; ++k)
            wp[c2 * 9 + k] = pack2(__ldg(&w[(2 * c2) * 9 + k]),
                                   __ldg(&w[(2 * c2 + 1) * 9 + k]));

    // qr[c] = conv(r, Wq[c], pad=1) -- loop-invariant, packed channel pairs
    u64 qr0p[5], qr1p[5];
#pragma unroll
    for (int c2 = 0; c2 < 5; ++c2) { qr0p[c2] = 0ull; qr1p[c2] = 0ull; }
#pragma unroll
    for (int k = 0; k < 9; ++k) {
        u64 n0 = ub0[p0 + OFF[k]];
        u64 n1 = ub0[p1 + OFF[k]];
#pragma unroll
        for (int c2 = 0; c2 < 5; ++c2) {
            u64 wq = pack2(__ldg(&Wq[(2 * c2) * 9 + k]),
                           __ldg(&Wq[(2 * c2 + 1) * 9 + k]));
            qr0p[c2] = fma2(wq, n0, qr0p[c2]);
            qr1p[c2] = fma2(wq, n1, qr1p[c2]);
        }
    }

    // v0 = max_c qr
    float v0, v1;
    {
        float2 t0 = unpack2(qr0p[0]), t1 = unpack2(qr1p[0]);
        v0 = fmaxf(t0.x, t0.y); v1 = fmaxf(t1.x, t1.y);
#pragma unroll
        for (int c2 = 1; c2 < 5; ++c2) {
            t0 = unpack2(qr0p[c2]); t1 = unpack2(qr1p[c2]);
            v0 = fmaxf(v0, fmaxf(t0.x, t0.y));
            v1 = fmaxf(v1, fmaxf(t1.x, t1.y));
        }
    }
    __syncwarp();                          // r readers done before overwrite
    ub0[i0] = pack2(v0, v0);
    ub0[i1] = pack2(v1, v1);

    // K-1 = 9 sweeps: v <- max_c( qr[c] + conv(v, w[c]) )
    const u64* src = ub0;
    u64* dst = ub1;
#pragma unroll 1
    for (int it = 0; it < KI - 1; ++it) {
        __syncwarp();
        u64 a0[5], a1[5];
#pragma unroll
        for (int k = 0; k < 9; ++k) {
            u64 n0 = src[p0 + OFF[k]];
            u64 n1 = src[p1 + OFF[k]];
            if (k == 0) {
#pragma unroll
                for (int c2 = 0; c2 < 5; ++c2) {
                    a0[c2] = fma2(wp[c2 * 9], n0, qr0p[c2]);
                    a1[c2] = fma2(wp[c2 * 9], n1, qr1p[c2]);
                }
            } else {
#pragma unroll
                for (int c2 = 0; c2 < 5; ++c2) {
                    a0[c2] = fma2(wp[c2 * 9 + k], n0, a0[c2]);
                    a1[c2] = fma2(wp[c2 * 9 + k], n1, a1[c2]);
                }
            }
        }
        float2 t0 = unpack2(a0[0]), t1 = unpack2(a1[0]);
        float m0 = fmaxf(t0.x, t0.y), m1 = fmaxf(t1.x, t1.y);
#pragma unroll
        for (int c2 = 1; c2 < 5; ++c2) {
            t0 = unpack2(a0[c2]); t1 = unpack2(a1[c2]);
            m0 = fmaxf(m0, fmaxf(t0.x, t0.y));
            m1 = fmaxf(m1, fmaxf(t1.x, t1.y));
        }
        dst[i0] = pack2(m0, m0);
        dst[i1] = pack2(m1, m1);
        u64* tmp = (u64*)src; src = dst; dst = tmp;
    }
    __syncwarp();

    // Final conv at the selected pixel + FC head (single owning lane)
    const int s1 = (int)Sb[64];
    const int s2 = (int)Sb[65];
    const int psel = s1 * 8 + s2;
    if (lane == (psel & 31)) {
        const bool hi = psel >= 32;
        const int pb = s1 * 10 + s2;       // window top-left for selected pixel
        u64 accp[5];
#pragma unroll
        for (int c2 = 0; c2 < 5; ++c2) accp[c2] = hi ? qr1p[c2] : qr0p[c2];
#pragma unroll
        for (int k = 0; k < 9; ++k) {
            u64 nn = src[pb + OFF[k]];
#pragma unroll
            for (int c2 = 0; c2 < 5; ++c2)
                accp[c2] = fma2(wp[c2 * 9 + k], nn, accp[c2]);
        }
        float lg[8];
#pragma unroll
        for (int j = 0; j < 8; ++j) lg[j] = 0.f;
#pragma unroll
        for (int c2 = 0; c2 < 5; ++c2) {
            float2 q = unpack2(accp[c2]);
#pragma unroll
            for (int j = 0; j < 8; ++j) {
                lg[j] = fmaf(q.x, __ldg(&Wfc[j * 10 + 2 * c2]), lg[j]);
                lg[j] = fmaf(q.y, __ldg(&Wfc[j * 10 + 2 * c2 + 1]), lg[j]);
            }
        }
#pragma unroll
        for (int j = 0; j < 8; ++j) out[(long long)b * 8 + j] = lg[j];
    }
}

extern "C" void kernel_launch(void* const* d_in, const int* in_sizes, int n_in,
                              void* d_out, int out_size) {
    const float* S   = (const float*)d_in[0];
    const float* Wh  = (const float*)d_in[1];
    const float* bh  = (const float*)d_in[2];
    const float* Wr  = (const float*)d_in[3];
    const float* Wq  = (const float*)d_in[4];
    const float* w   = (const float*)d_in[5];
    const float* Wfc = (const float*)d_in[6];
    float* out = (float*)d_out;

    const int B = in_sizes[0] / 66;

    weff_kernel<<<1, 320>>>(Wh, bh, Wr);
    const int grid = (B + NWARP - 1) / NWARP;
    vin_kernel<<<grid, NWARP * 32>>>(S, Wq, w, Wfc, out, B);
}

// round 3
// speedup vs baseline: 1.0574x; 1.0280x over previous
#include <cuda_runtime.h>

typedef unsigned long long u64;

#define LH 150
#define LQ 10
#define KI 10
#define NWARP 12
#define PSTR 12              // pair-row stride in u64 words (conflict-free mod 16)
#define PBUF (6 * PSTR)      // 6 pair-rows x 12 words = 72 u64 per buffer

// ---- packed f32x2 helpers -------------------------------------------------
__device__ __forceinline__ u64 fma2(u64 a, u64 b, u64 c) {
    u64 d;
    asm("fma.rn.f32x2 %0, %1, %2, %3;" : "=l"(d) : "l"(a), "l"(b), "l"(c));
    return d;
}
__device__ __forceinline__ u64 pack2(float lo, float hi) {
    u64 r;
    asm("mov.b64 %0, {%1, %2};" : "=l"(r) : "f"(lo), "f"(hi));
    return r;
}
__device__ __forceinline__ float2 unpack2(u64 p) {
    float2 v;
    asm("mov.b64 {%0, %1}, %2;" : "=f"(v.x), "=f"(v.y) : "l"(p));
    return v;
}

// One warp per batch element. Lane l = (y0,x0), y0=l>>3, x0=l&7, owns pixels
// (y0,x0) and (y0+4,x0).
//
// v-grid SMEM layout ("pair-rows"): cell[R][xc] = {v(R-1, xc-1), v(R+3, xc-1)},
// R in 0..5, xc in 0..9 (cols -1..8).  prow[0]={0, row3}, prow[5]={row4, 0};
// border cols stay zero.  One LDS.64 yields the neighbor value for BOTH owned
// pixels (p0 reads .x, p1 reads .y).  Stride 12 u64/row makes every 3x3-window
// gather bank-conflict-free.
//
// Channels are paired (c,c+1) into packed weights (90 regs) and packed
// accumulators; inner loop = 9 LDS.64 + 18 splat movs + 90 FFMA2 + scalar max.
__global__ __launch_bounds__(NWARP * 32)
void vin_kernel(const float* __restrict__ S,
                const float* __restrict__ Wh,
                const float* __restrict__ bh,
                const float* __restrict__ Wr,
                const float* __restrict__ Wq,
                const float* __restrict__ w,
                const float* __restrict__ Wfc,
                float* __restrict__ out, int B) {
    __shared__ u64 sbuf[NWARP][2][PBUF];
    __shared__ float sweff[10];

    const int warp = threadIdx.x >> 5;
    const int lane = threadIdx.x & 31;

    // Block-local weff: collapse 150-ch hidden conv + 1x1 readout into one
    // 3x3 kernel + bias.  Warps 0..9 each produce one output via strided dot.
    if (warp < 10) {
        float acc = 0.f;
        for (int c = lane; c < LH; c += 32) {
            float x = (warp < 9) ? __ldg(&Wh[c * 9 + warp]) : __ldg(&bh[c]);
            acc = fmaf(__ldg(&Wr[c]), x, acc);
        }
#pragma unroll
        for (int off = 16; off >= 1; off >>= 1)
            acc += __shfl_xor_sync(0xffffffffu, acc, off);
        if (lane == 0) sweff[warp] = acc;
    }
    __syncthreads();

    const int b = blockIdx.x * NWARP + warp;
    if (b >= B) return;                    // warp-uniform; no more block syncs
    const float* Sb = S + (long long)b * 66;

    u64* ub0 = sbuf[warp][0];
    u64* ub1 = sbuf[warp][1];

    const int y0 = lane >> 3, x0 = lane & 7;
    const int p  = y0 * PSTR + x0;         // window base (R=y0+dy, xc=x0+dx)
    const int ist = p + PSTR + 1;          // own store cell: R=y0+1, xc=x0+1
    const int OFF[9] = {0, 1, 2, PSTR, PSTR + 1, PSTR + 2,
                        2 * PSTR, 2 * PSTR + 1, 2 * PSTR + 2};

    // Zero both buffers (borders stay zero forever -> implicit pad)
#pragma unroll
    for (int i = 0; i < 5; ++i) {
        int idx = lane + 32 * i;
        if (idx < PBUF) { ub0[idx] = 0ull; ub1[idx] = 0ull; }
    }
    __syncwarp();

    // Stage X as pair-rows
    float xa = Sb[lane], xb = Sb[lane + 32];
    ub0[ist] = pack2(xa, xb);
    if (y0 == 0) ub0[5 * PSTR + 1 + x0] = pack2(xb, 0.f);   // prow[5]={row4,0}
    if (y0 == 3) ub0[1 + x0]            = pack2(0.f, xa);   // prow[0]={0,row3}
    __syncwarp();

    // r = conv(X, W_eff, pad=1) + b_eff
    float r0 = sweff[9], r1 = r0;
#pragma unroll
    for (int k = 0; k < 9; ++k) {
        float2 n = unpack2(ub0[p + OFF[k]]);
        r0 = fmaf(sweff[k], n.x, r0);
        r1 = fmaf(sweff[k], n.y, r1);
    }
    __syncwarp();
    ub0[ist] = pack2(r0, r1);
    if (y0 == 0) ub0[5 * PSTR + 1 + x0] = pack2(r1, 0.f);
    if (y0 == 3) ub0[1 + x0]            = pack2(0.f, r0);
    __syncwarp();

    // Packed transition weights wp[c2][k] = {w[2c2][k], w[2c2+1][k]}
    u64 wp[45];
#pragma unroll
    for (int c2 = 0; c2 < 5; ++c2)
#pragma unroll
        for (int k = 0; k < 9; ++k)
            wp[c2 * 9 + k] = pack2(__ldg(&w[(2 * c2) * 9 + k]),
                                   __ldg(&w[(2 * c2 + 1) * 9 + k]));

    // qr[c] = conv(r, Wq[c], pad=1) -- loop-invariant, channel-packed
    u64 qr0p[5], qr1p[5];
#pragma unroll
    for (int c2 = 0; c2 < 5; ++c2) { qr0p[c2] = 0ull; qr1p[c2] = 0ull; }
#pragma unroll
    for (int k = 0; k < 9; ++k) {
        float2 nf = unpack2(ub0[p + OFF[k]]);
        u64 n0 = pack2(nf.x, nf.x);
        u64 n1 = pack2(nf.y, nf.y);
#pragma unroll
        for (int c2 = 0; c2 < 5; ++c2) {
            u64 wq = pack2(__ldg(&Wq[(2 * c2) * 9 + k]),
                           __ldg(&Wq[(2 * c2 + 1) * 9 + k]));
            qr0p[c2] = fma2(wq, n0, qr0p[c2]);
            qr1p[c2] = fma2(wq, n1, qr1p[c2]);
        }
    }

    // v0 = max_c qr
    float v0, v1;
    {
        float2 t0 = unpack2(qr0p[0]), t1 = unpack2(qr1p[0]);
        v0 = fmaxf(t0.x, t0.y); v1 = fmaxf(t1.x, t1.y);
#pragma unroll
        for (int c2 = 1; c2 < 5; ++c2) {
            t0 = unpack2(qr0p[c2]); t1 = unpack2(qr1p[c2]);
            v0 = fmaxf(v0, fmaxf(t0.x, t0.y));
            v1 = fmaxf(v1, fmaxf(t1.x, t1.y));
        }
    }
    __syncwarp();                          // r readers done before overwrite
    ub0[ist] = pack2(v0, v1);
    if (y0 == 0) ub0[5 * PSTR + 1 + x0] = pack2(v1, 0.f);
    if (y0 == 3) ub0[1 + x0]            = pack2(0.f, v0);

    // K-1 = 9 sweeps: v <- max_c( qr[c] + conv(v, w[c]) )
    const u64* src = ub0;
    u64* dst = ub1;
#pragma unroll 1
    for (int it = 0; it < KI - 1; ++it) {
        __syncwarp();
        u64 a0[5], a1[5];
#pragma unroll
        for (int k = 0; k < 9; ++k) {
            float2 nf = unpack2(src[p + OFF[k]]);
            u64 n0 = pack2(nf.x, nf.x);
            u64 n1 = pack2(nf.y, nf.y);
            if (k == 0) {
#pragma unroll
                for (int c2 = 0; c2 < 5; ++c2) {
                    a0[c2] = fma2(wp[c2 * 9], n0, qr0p[c2]);
                    a1[c2] = fma2(wp[c2 * 9], n1, qr1p[c2]);
                }
            } else {
#pragma unroll
                for (int c2 = 0; c2 < 5; ++c2) {
                    a0[c2] = fma2(wp[c2 * 9 + k], n0, a0[c2]);
                    a1[c2] = fma2(wp[c2 * 9 + k], n1, a1[c2]);
                }
            }
        }
        float2 t0 = unpack2(a0[0]), t1 = unpack2(a1[0]);
        float m0 = fmaxf(t0.x, t0.y), m1 = fmaxf(t1.x, t1.y);
#pragma unroll
        for (int c2 = 1; c2 < 5; ++c2) {
            t0 = unpack2(a0[c2]); t1 = unpack2(a1[c2]);
            m0 = fmaxf(m0, fmaxf(t0.x, t0.y));
            m1 = fmaxf(m1, fmaxf(t1.x, t1.y));
        }
        dst[ist] = pack2(m0, m1);
        if (y0 == 0) dst[5 * PSTR + 1 + x0] = pack2(m1, 0.f);
        if (y0 == 3) dst[1 + x0]            = pack2(0.f, m0);
        u64* tmp = (u64*)src; src = dst; dst = tmp;
    }
    __syncwarp();

    // Final conv at the selected pixel + FC head (single owning lane)
    const int s1 = (int)Sb[64];
    const int s2 = (int)Sb[65];
    const int psel = s1 * 8 + s2;
    if (lane == (psel & 31)) {
        const bool hi = psel >= 32;
        u64 accp[5];
#pragma unroll
        for (int c2 = 0; c2 < 5; ++c2) accp[c2] = hi ? qr1p[c2] : qr0p[c2];
#pragma unroll
        for (int k = 0; k < 9; ++k) {
            const int dy = k / 3, dx = k % 3;
            const int rr = s1 - 1 + dy;          // actual grid row, -1..8
            const int xc = s2 + dx;              // padded col, 0..9
            float nn;
            if (rr <= 3) nn = unpack2(src[(rr + 1) * PSTR + xc]).x;
            else         nn = unpack2(src[(rr - 3) * PSTR + xc]).y;
            u64 np = pack2(nn, nn);
#pragma unroll
            for (int c2 = 0; c2 < 5; ++c2)
                accp[c2] = fma2(wp[c2 * 9 + k], np, accp[c2]);
        }
        float lg[8];
#pragma unroll
        for (int j = 0; j < 8; ++j) lg[j] = 0.f;
#pragma unroll
        for (int c2 = 0; c2 < 5; ++c2) {
            float2 q = unpack2(accp[c2]);
#pragma unroll
            for (int j = 0; j < 8; ++j) {
                lg[j] = fmaf(q.x, __ldg(&Wfc[j * 10 + 2 * c2]), lg[j]);
                lg[j] = fmaf(q.y, __ldg(&Wfc[j * 10 + 2 * c2 + 1]), lg[j]);
            }
        }
#pragma unroll
        for (int j = 0; j < 8; ++j) out[(long long)b * 8 + j] = lg[j];
    }
}

extern "C" void kernel_launch(void* const* d_in, const int* in_sizes, int n_in,
                              void* d_out, int out_size) {
    const float* S   = (const float*)d_in[0];
    const float* Wh  = (const float*)d_in[1];
    const float* bh  = (const float*)d_in[2];
    const float* Wr  = (const float*)d_in[3];
    const float* Wq  = (const float*)d_in[4];
    const float* w   = (const float*)d_in[5];
    const float* Wfc = (const float*)d_in[6];
    float* out = (float*)d_out;

    const int B = in_sizes[0] / 66;
    const int grid = (B + NWARP - 1) / NWARP;
    vin_kernel<<<grid, NWARP * 32>>>(S, Wh, bh, Wr, Wq, w, Wfc, out, B);
}